// round 11
// baseline (speedup 1.0000x reference)
#include <cuda_runtime.h>
#include <math.h>

#define T_  128
#define B_  32
#define I_  128
#define H_  128
#define R_  100
#define O_  64
#define RH_ (R_*H_)       // 12800
#define COLS_ (H_*B_)     // 4096 flat (k*32+b) columns per region

typedef unsigned long long u64;

// Scratch (static device globals)
static __device__ float g_xT [(size_t)T_*B_*I_];      // [t][i*32+b]
static __device__ float g_P  [(size_t)R_*B_*H_];      // [r][b*128+g]
static __device__ float g_Hbr[(size_t)T_*B_*RH_];     // [t][b][r*128+g] (out)
static __device__ float g_Hkb[(size_t)T_*R_*COLS_];   // [t][r][k*32+b]
static __device__ float g_msg[(size_t)R_*COLS_];      // [j][k*32+b]

// ---- packed f32x2 helpers (sm_103a) ----
__device__ __forceinline__ u64 pk2(float lo, float hi){
    u64 r; asm("mov.b64 %0, {%1,%2};" : "=l"(r) : "f"(lo), "f"(hi)); return r;
}
__device__ __forceinline__ void up2(u64 v, float& lo, float& hi){
    asm("mov.b64 {%0,%1}, %2;" : "=f"(lo), "=f"(hi) : "l"(v));
}
__device__ __forceinline__ u64 fma2(u64 a, u64 b, u64 c){
    u64 d; asm("fma.rn.f32x2 %0, %1, %2, %3;" : "=l"(d) : "l"(a), "l"(b), "l"(c)); return d;
}
__device__ __forceinline__ float tanha(float x){
    float y; asm("tanh.approx.f32 %0, %1;" : "=f"(y) : "f"(x)); return y;
}

// ============================================================================
// xprep: transpose x[t][b][i] -> g_xT[t][i*32+b]  (grid T_, 256 thr)
// ============================================================================
__global__ __launch_bounds__(256) void xprep_kernel(const float* __restrict__ x){
    __shared__ float xsh[32][129];
    int t = blockIdx.x;
    const float* xt = x + (size_t)t*B_*I_;
    for (int idx = threadIdx.x; idx < B_*I_; idx += 256)
        xsh[idx>>7][idx&127] = xt[idx];
    __syncthreads();
    float* dst = g_xT + (size_t)t*B_*I_;
    for (int idx = threadIdx.x; idx < B_*I_; idx += 256)
        dst[idx] = xsh[idx&31][idx>>5];          // idx = i*32+b
}

// ============================================================================
// K1: grid 528 x 128 thr, 40KB dyn smem.
//  blocks 0..399  : (r = bx>>2, gq = bx&3): P[r][:, 32g-slice] =
//                   bias + x_t @ W_ih + H[t-1] @ W_hh
//  blocks 400..527: msg strip (32 cols) = C^T H[t-1]
// ============================================================================
#define K1_SMEM_FLOATS 10240   // region: sx(4096)+sh(4096); msg: C(10000)

__global__ __launch_bounds__(128) void k1_kernel(const float* __restrict__ W_ih,
                                                 const float* __restrict__ W_hh,
                                                 const float* __restrict__ C,
                                                 const float* __restrict__ bias,
                                                 int t){
    extern __shared__ float sm[];
    const int bx = blockIdx.x, tid = threadIdx.x;

    if (bx < 400){
        // -------------------- region block --------------------
        const int r  = bx >> 2;
        const int gq = bx & 3;
        const int g0 = gq*32 + (tid >> 4)*4;   // 4 g-cols
        const int bp = tid & 15;               // b-pair index: b = 2bp, 2bp+1
        float2* sx = reinterpret_cast<float2*>(sm);          // [k*16+bp] pre-paired
        float2* sh = reinterpret_cast<float2*>(sm + 4096);

        // stage x_t (and H[t-1]) pre-paired: float4 -> two float2 pairs
        {
            const float4* xsrc = reinterpret_cast<const float4*>(g_xT + (size_t)t*B_*I_);
#pragma unroll
            for (int it=0; it<8; it++){
                int q = tid + it*128;                 // q: k = q>>3, bq = q&7
                float4 v = __ldcg(xsrc + q);
                int d = (q>>3)*16 + (q&7)*2;
                sx[d]   = make_float2(v.x, v.y);
                sx[d+1] = make_float2(v.z, v.w);
            }
            if (t > 0){
                const float4* hsrc = reinterpret_cast<const float4*>(
                    g_Hkb + ((size_t)(t-1)*R_ + r)*COLS_);
#pragma unroll
                for (int it=0; it<8; it++){
                    int q = tid + it*128;
                    float4 v = __ldcg(hsrc + q);
                    int d = (q>>3)*16 + (q&7)*2;
                    sh[d]   = make_float2(v.x, v.y);
                    sh[d+1] = make_float2(v.z, v.w);
                }
            }
        }
        __syncthreads();

        u64 a0,a1,a2,a3;                    // {g0,g0+1},{g0+2,g0+3} x {b even, b odd}
        {
            float4 bv = *reinterpret_cast<const float4*>(bias + r*H_ + g0);
            a0 = pk2(bv.x,bv.y); a1 = pk2(bv.z,bv.w); a2 = a0; a3 = a1;
        }
        // x @ W_ih
        {
            const ulonglong2* wx = reinterpret_cast<const ulonglong2*>(
                W_ih + (size_t)r*I_*H_ + g0);
#pragma unroll 8
            for (int k=0;k<I_;k++){
                ulonglong2 w = wx[(size_t)k*32];
                float2 xp = sx[k*16 + bp];
                u64 x0 = pk2(xp.x,xp.x), x1 = pk2(xp.y,xp.y);
                a0 = fma2(w.x, x0, a0);  a1 = fma2(w.y, x0, a1);
                a2 = fma2(w.x, x1, a2);  a3 = fma2(w.y, x1, a3);
            }
        }
        // H[t-1] @ W_hh
        if (t > 0){
            const ulonglong2* wh = reinterpret_cast<const ulonglong2*>(
                W_hh + (size_t)r*H_*H_ + g0);
#pragma unroll 8
            for (int k=0;k<H_;k++){
                ulonglong2 w = wh[(size_t)k*32];
                float2 hp = sh[k*16 + bp];
                u64 h0 = pk2(hp.x,hp.x), h1 = pk2(hp.y,hp.y);
                a0 = fma2(w.x, h0, a0);  a1 = fma2(w.y, h0, a1);
                a2 = fma2(w.x, h1, a2);  a3 = fma2(w.y, h1, a3);
            }
        }
        const int b0 = bp*2;
        ulonglong2 v0; v0.x=a0; v0.y=a1;
        ulonglong2 v1; v1.x=a2; v1.y=a3;
        *reinterpret_cast<ulonglong2*>(g_P + (size_t)r*4096 + (size_t)b0*H_ + g0)     = v0;
        *reinterpret_cast<ulonglong2*>(g_P + (size_t)r*4096 + (size_t)(b0+1)*H_ + g0) = v1;
    } else {
        // -------------------- msg block --------------------
        if (t == 0) return;
        float* Cs = sm;                          // 10000 floats
        const int m = bx - 400;                  // 0..127
        const int col0 = m*32;
        {
            const float4* c4 = reinterpret_cast<const float4*>(C);
            float4* cd = reinterpret_cast<float4*>(Cs);
            for (int i=tid;i<2500;i+=128) cd[i]=c4[i];
        }
        __syncthreads();

        const int col = tid & 31;
        const int jg  = tid >> 5;                          // 0..3
        const int njp = (jg < 2) ? 13 : 12;
        const int jp0 = (jg < 2) ? jg*13 : 26 + (jg-2)*12; // 13+13+12+12 = 50
        const int colg = col0 + col;

        u64 acc[13];
#pragma unroll
        for (int j=0;j<13;j++) acc[j] = 0ull;

        const float* Hb = g_Hkb + (size_t)(t-1)*R_*COLS_ + colg;
#pragma unroll 2
        for (int i=0;i<R_;i++){
            float h = __ldcg(Hb + (size_t)i*COLS_);        // coalesced across col
            u64 h2 = pk2(h, h);
            const float* Cr = Cs + i*R_ + jp0*2;
#pragma unroll
            for (int j=0;j<13;j++){
                if (j < njp){
                    u64 Cv = *reinterpret_cast<const u64*>(Cr + 2*j);
                    acc[j] = fma2(Cv, h2, acc[j]);
                }
            }
        }
#pragma unroll
        for (int j=0;j<13;j++){
            if (j < njp){
                float lo, hi; up2(acc[j], lo, hi);
                int jj = (jp0 + j)*2;
                __stcg(&g_msg[(size_t)jj*COLS_     + colg], lo);
                __stcg(&g_msg[(size_t)(jj+1)*COLS_ + colg], hi);
            }
        }
    }
}

// ============================================================================
// K2: grid 400 x 128 thr. (r = bx>>2, gq = bx&3):
//     H[t][:, 32g-slice] = tanh(P + msg[r] @ W_rhh[r]); dual-layout store
// ============================================================================
__global__ __launch_bounds__(128) void k2_kernel(const float* __restrict__ W_rhh,
                                                 int t){
    __shared__ float2 ms[2048];                  // [k*16+bp] pre-paired
    const int bx = blockIdx.x, tid = threadIdx.x;
    const int r  = bx >> 2;
    const int gq = bx & 3;
    const int g0 = gq*32 + (tid >> 4)*4;
    const int bp = tid & 15;
    const int b0 = bp*2;

    if (t > 0){
        const float4* msrc = reinterpret_cast<const float4*>(g_msg + (size_t)r*COLS_);
#pragma unroll
        for (int it=0; it<8; it++){
            int q = tid + it*128;
            float4 v = __ldcg(msrc + q);
            int d = (q>>3)*16 + (q&7)*2;
            ms[d]   = make_float2(v.x, v.y);
            ms[d+1] = make_float2(v.z, v.w);
        }
        __syncthreads();
    }

    u64 a0,a1,a2,a3;
    {
        ulonglong2 p0 = *reinterpret_cast<const ulonglong2*>(
            g_P + (size_t)r*4096 + (size_t)b0*H_ + g0);
        ulonglong2 p1 = *reinterpret_cast<const ulonglong2*>(
            g_P + (size_t)r*4096 + (size_t)(b0+1)*H_ + g0);
        a0=p0.x; a1=p0.y; a2=p1.x; a3=p1.y;
    }
    if (t > 0){
        const ulonglong2* wc = reinterpret_cast<const ulonglong2*>(
            W_rhh + (size_t)r*H_*H_ + g0);
#pragma unroll 8
        for (int k=0;k<H_;k++){
            ulonglong2 w = wc[(size_t)k*32];
            float2 mp = ms[k*16 + bp];
            u64 m0 = pk2(mp.x,mp.x), m1 = pk2(mp.y,mp.y);
            a0 = fma2(w.x, m0, a0);  a1 = fma2(w.y, m0, a1);
            a2 = fma2(w.x, m1, a2);  a3 = fma2(w.y, m1, a3);
        }
    }
    float d0,d1,d2,d3, e0,e1,e2,e3;
    up2(a0,d0,d1); up2(a1,d2,d3); up2(a2,e0,e1); up2(a3,e2,e3);
    d0=tanha(d0); d1=tanha(d1); d2=tanha(d2); d3=tanha(d3);
    e0=tanha(e0); e1=tanha(e1); e2=tanha(e2); e3=tanha(e3);

    float* Hbr = g_Hbr + (size_t)t*B_*RH_ + (size_t)r*H_;
    __stcg(reinterpret_cast<float4*>(Hbr + (size_t)b0*RH_ + g0),
           make_float4(d0,d1,d2,d3));
    __stcg(reinterpret_cast<float4*>(Hbr + (size_t)(b0+1)*RH_ + g0),
           make_float4(e0,e1,e2,e3));
    float* Hkb = g_Hkb + ((size_t)t*R_ + r)*COLS_;
    __stcg(reinterpret_cast<float2*>(Hkb + (g0+0)*32 + b0), make_float2(d0,e0));
    __stcg(reinterpret_cast<float2*>(Hkb + (g0+1)*32 + b0), make_float2(d1,e1));
    __stcg(reinterpret_cast<float2*>(Hkb + (g0+2)*32 + b0), make_float2(d2,e2));
    __stcg(reinterpret_cast<float2*>(Hkb + (g0+3)*32 + b0), make_float2(d3,e3));
}

// ============================================================================
// out[t,b,o] = H[t][b][:] @ W_out + b_out   grid (T,2), 128 thr
// ============================================================================
__global__ __launch_bounds__(128) void out_kernel(const float* __restrict__ W_out,
                                                  const float* __restrict__ b_out,
                                                  float* __restrict__ out){
    int t = blockIdx.x, bh = blockIdx.y;
    __shared__ u64 hsh[128][9];
    int tid = threadIdx.x;
    int og = tid & 15, rp = tid >> 4;
    int o0 = og*4;
    u64 acc[4];
    {
        const u64* bo = reinterpret_cast<const u64*>(b_out + o0);
        acc[0]=bo[0]; acc[1]=bo[1]; acc[2]=bo[0]; acc[3]=bo[1];
    }
    const float* Hb = g_Hbr + (size_t)t*B_*RH_ + (size_t)(bh*16)*RH_;
    for (int kt=0; kt<RH_/128; kt++){
        __syncthreads();
        for (int idx = tid; idx < 16*128; idx += 128){
            int b = idx >> 7, kk = idx & 127;
            reinterpret_cast<float*>(&hsh[kk][b>>1])[b&1] = Hb[(size_t)b*RH_ + kt*128 + kk];
        }
        __syncthreads();
#pragma unroll 4
        for (int kk=0; kk<128; kk++){
            int k = kt*128 + kk;
            ulonglong2 w = *reinterpret_cast<const ulonglong2*>(W_out + (size_t)k*O_ + o0);
            u64 hp = hsh[kk][rp];
            float h0, h1; up2(hp, h0, h1);
            u64 h0d = pk2(h0,h0), h1d = pk2(h1,h1);
            acc[0] = fma2(w.x, h0d, acc[0]);  acc[1] = fma2(w.y, h0d, acc[1]);
            acc[2] = fma2(w.x, h1d, acc[2]);  acc[3] = fma2(w.y, h1d, acc[3]);
        }
    }
    u64* op = reinterpret_cast<u64*>(out);
    int row0 = bh*16 + rp*2;
    size_t base0 = ((size_t)(t*B_ + row0  )*O_ + o0) >> 1;
    size_t base1 = ((size_t)(t*B_ + row0+1)*O_ + o0) >> 1;
    op[base0] = acc[0];  op[base0+1] = acc[1];
    op[base1] = acc[2];  op[base1+1] = acc[3];
}

// ============================================================================
// Launch: xprep, 128 x (K1 -> K2) hw-synced graph nodes, out.
// ============================================================================
extern "C" void kernel_launch(void* const* d_in, const int* in_sizes, int n_in,
                              void* d_out, int out_size){
    const float* x     = (const float*)d_in[0];
    const float* C     = (const float*)d_in[1];
    const float* W_ih  = (const float*)d_in[2];
    const float* W_hh  = (const float*)d_in[3];
    const float* W_rhh = (const float*)d_in[4];
    const float* bias  = (const float*)d_in[5];
    const float* W_out = (const float*)d_in[6];
    const float* b_out = (const float*)d_in[7];
    float* out = (float*)d_out;

    xprep_kernel<<<T_, 256>>>(x);

    for (int t = 0; t < T_; t++){
        k1_kernel<<<528, 128, K1_SMEM_FLOATS * sizeof(float)>>>(W_ih, W_hh, C, bias, t);
        k2_kernel<<<400, 128>>>(W_rhh, t);
    }

    out_kernel<<<dim3(T_, 2), 128>>>(W_out, b_out, out);
}

// round 12
// speedup vs baseline: 1.7178x; 1.7178x over previous
#include <cuda_runtime.h>
#include <math.h>

#define T_  128
#define B_  32
#define I_  128
#define H_  128
#define R_  100
#define O_  64
#define RH_ (R_*H_)       // 12800
#define COLS_ (H_*B_)     // 4096 flat (k*32+b) columns per region

typedef unsigned long long u64;

// Scratch (static device globals)
static __device__ float g_xP [(size_t)T_*4096];       // [t][i*16+bp] float2 pairs
static __device__ float g_P  [(size_t)R_*B_*H_];      // [r][b*128+g]
static __device__ float g_Hbr[(size_t)T_*B_*RH_];     // [t][b][r*128+g] (out)
static __device__ float g_Hkb[(size_t)T_*R_*COLS_];   // [t][r][k*32+b]
static __device__ float g_msg[(size_t)R_*COLS_];      // [j][k*32+b]

// ---- packed f32x2 helpers (sm_103a) ----
__device__ __forceinline__ u64 pk2(float lo, float hi){
    u64 r; asm("mov.b64 %0, {%1,%2};" : "=l"(r) : "f"(lo), "f"(hi)); return r;
}
__device__ __forceinline__ void up2(u64 v, float& lo, float& hi){
    asm("mov.b64 {%0,%1}, %2;" : "=f"(lo), "=f"(hi) : "l"(v));
}
__device__ __forceinline__ u64 fma2(u64 a, u64 b, u64 c){
    u64 d; asm("fma.rn.f32x2 %0, %1, %2, %3;" : "=l"(d) : "l"(a), "l"(b), "l"(c)); return d;
}
__device__ __forceinline__ float tanha(float x){
    float y; asm("tanh.approx.f32 %0, %1;" : "=f"(y) : "f"(x)); return y;
}

// ============================================================================
// xprep: x[t][b][i] -> g_xP[t][i*16+bp] = {x[2bp][i], x[2bp+1][i]}
// ============================================================================
__global__ __launch_bounds__(256) void xprep_kernel(const float* __restrict__ x){
    __shared__ float xsh[32][129];
    int t = blockIdx.x;
    const float* xt = x + (size_t)t*B_*I_;
    for (int idx = threadIdx.x; idx < B_*I_; idx += 256)
        xsh[idx>>7][idx&127] = xt[idx];
    __syncthreads();
    float2* dst = reinterpret_cast<float2*>(g_xP + (size_t)t*4096);
    for (int q = threadIdx.x; q < 2048; q += 256){
        int i = q >> 4, bp = q & 15;
        dst[q] = make_float2(xsh[2*bp][i], xsh[2*bp+1][i]);
    }
}

// ============================================================================
// K1: grid 528 x 128 thr, 64KB dyn smem.
//  blocks 0..399  : (r = bx>>2, gq = bx&3): P[r][:, 32g-slice] =
//                   bias + x_t @ W_ih + H[t-1] @ W_hh   (ALL operands in smem)
//  blocks 400..527: msg strip (32 cols) = C^T H[t-1]    (C + H-strip in smem)
// ============================================================================
#define K1_SMEM_FLOATS 16384   // 64 KB

__global__ __launch_bounds__(128) void k1_kernel(const float* __restrict__ W_ih,
                                                 const float* __restrict__ W_hh,
                                                 const float* __restrict__ C,
                                                 const float* __restrict__ bias,
                                                 int t){
    extern __shared__ float sm[];
    const int bx = blockIdx.x, tid = threadIdx.x;

    if (bx < 400){
        // -------------------- region block --------------------
        const int r  = bx >> 2;
        const int gq = bx & 3;
        float*  sw1 = sm;                                   // [k*32 + c] W_ih slice
        float*  sw2 = sm + 4096;                            // W_hh slice
        float2* sx  = reinterpret_cast<float2*>(sm + 8192); // [k*16+bp]
        float2* sh  = reinterpret_cast<float2*>(sm + 12288);

        // stage W slices (rows of 8 float4 each, coalesced)
        {
            const float4* w1s = reinterpret_cast<const float4*>(W_ih + (size_t)r*I_*H_) + gq*8;
            const float4* w2s = reinterpret_cast<const float4*>(W_hh + (size_t)r*H_*H_) + gq*8;
            float4* d1 = reinterpret_cast<float4*>(sw1);
            float4* d2 = reinterpret_cast<float4*>(sw2);
#pragma unroll
            for (int it=0; it<8; it++){
                int q = tid + it*128;           // q = k*8 + c4
                int k = q >> 3, c4 = q & 7;
                d1[q] = __ldcg(w1s + (size_t)k*32 + c4);
                d2[q] = __ldcg(w2s + (size_t)k*32 + c4);
            }
            // x pairs: direct copy (already paired)
            const float4* xsrc = reinterpret_cast<const float4*>(g_xP + (size_t)t*4096);
            float4* dx = reinterpret_cast<float4*>(sx);
#pragma unroll
            for (int it=0; it<8; it++) dx[tid + it*128] = __ldcg(xsrc + tid + it*128);
            if (t > 0){
                // H pairs: g_Hkb [k*32+b] reinterpreted as float2[k*16+bp] — direct copy
                const float4* hsrc = reinterpret_cast<const float4*>(
                    g_Hkb + ((size_t)(t-1)*R_ + r)*COLS_);
                float4* dh = reinterpret_cast<float4*>(sh);
#pragma unroll
                for (int it=0; it<8; it++) dh[tid + it*128] = __ldcg(hsrc + tid + it*128);
            }
        }
        __syncthreads();

        const int bp = tid & 15, b0 = bp*2;
        const int gi = tid >> 4;                 // float4-index within 32-col slice
        const int g0 = gq*32 + gi*4;
        const ulonglong2* w1u = reinterpret_cast<const ulonglong2*>(sw1);  // [k*8+gi]
        const ulonglong2* w2u = reinterpret_cast<const ulonglong2*>(sw2);

        u64 a0,a1,a2,a3;
        {
            float4 bv = *reinterpret_cast<const float4*>(bias + r*H_ + g0);
            a0 = pk2(bv.x,bv.y); a1 = pk2(bv.z,bv.w); a2 = a0; a3 = a1;
        }
#pragma unroll 4
        for (int k=0;k<I_;k++){
            ulonglong2 w = w1u[k*8 + gi];
            float2 xp = sx[k*16 + bp];
            u64 x0 = pk2(xp.x,xp.x), x1 = pk2(xp.y,xp.y);
            a0 = fma2(w.x, x0, a0);  a1 = fma2(w.y, x0, a1);
            a2 = fma2(w.x, x1, a2);  a3 = fma2(w.y, x1, a3);
        }
        if (t > 0){
#pragma unroll 4
            for (int k=0;k<H_;k++){
                ulonglong2 w = w2u[k*8 + gi];
                float2 hp = sh[k*16 + bp];
                u64 h0 = pk2(hp.x,hp.x), h1 = pk2(hp.y,hp.y);
                a0 = fma2(w.x, h0, a0);  a1 = fma2(w.y, h0, a1);
                a2 = fma2(w.x, h1, a2);  a3 = fma2(w.y, h1, a3);
            }
        }
        ulonglong2 v0; v0.x=a0; v0.y=a1;
        ulonglong2 v1; v1.x=a2; v1.y=a3;
        *reinterpret_cast<ulonglong2*>(g_P + (size_t)r*4096 + (size_t)b0*H_ + g0)     = v0;
        *reinterpret_cast<ulonglong2*>(g_P + (size_t)r*4096 + (size_t)(b0+1)*H_ + g0) = v1;
    } else {
        // -------------------- msg block --------------------
        if (t == 0) return;
        float* Cs = sm;                      // 10000 floats
        float* Hs = sm + 10000;              // [i*32 + c], 3200 floats
        const int m = bx - 400;              // 0..127
        const int col0 = m*32;
        {
            const float4* c4 = reinterpret_cast<const float4*>(C);
            float4* cd = reinterpret_cast<float4*>(Cs);
            for (int i=tid;i<2500;i+=128) cd[i] = __ldcg(c4 + i);
            const float* Hb = g_Hkb + (size_t)(t-1)*R_*COLS_ + col0;
            float4* hd = reinterpret_cast<float4*>(Hs);
            for (int idx=tid; idx<800; idx+=128){
                int i = idx >> 3, c4i = idx & 7;
                hd[idx] = __ldcg(reinterpret_cast<const float4*>(Hb + (size_t)i*COLS_) + c4i);
            }
        }
        __syncthreads();

        const int col = tid & 31;
        const int jg  = tid >> 5;                          // 0..3
        const int njp = (jg < 2) ? 13 : 12;
        const int jp0 = (jg < 2) ? jg*13 : 26 + (jg-2)*12; // 50 pairs
        const int colg = col0 + col;

        u64 acc[13];
#pragma unroll
        for (int j=0;j<13;j++) acc[j] = 0ull;
#pragma unroll 2
        for (int i=0;i<R_;i++){
            float h = Hs[i*32 + col];
            u64 h2 = pk2(h, h);
            const u64* Cr = reinterpret_cast<const u64*>(Cs + i*R_ + jp0*2);
#pragma unroll
            for (int j=0;j<13;j++){
                if (j < njp) acc[j] = fma2(Cr[j], h2, acc[j]);
            }
        }
#pragma unroll
        for (int j=0;j<13;j++){
            if (j < njp){
                float lo, hi; up2(acc[j], lo, hi);
                int jj = (jp0 + j)*2;
                __stcg(&g_msg[(size_t)jj*COLS_     + colg], lo);
                __stcg(&g_msg[(size_t)(jj+1)*COLS_ + colg], hi);
            }
        }
    }
}

// ============================================================================
// K2: grid 400 x 128 thr, 32KB smem. (r,gq): H[t] slice = tanh(P + msg@W_rhh)
// ============================================================================
#define K2_SMEM_FLOATS 8192    // 32 KB

__global__ __launch_bounds__(128) void k2_kernel(const float* __restrict__ W_rhh,
                                                 int t){
    extern __shared__ float sm[];
    float*  sw  = sm;                                    // [k*32+c] W_rhh slice
    float2* sms = reinterpret_cast<float2*>(sm + 4096);  // [k*16+bp] msg pairs

    const int bx = blockIdx.x, tid = threadIdx.x;
    const int r  = bx >> 2;
    const int gq = bx & 3;
    const int bp = tid & 15, b0 = bp*2;
    const int gi = tid >> 4;
    const int g0 = gq*32 + gi*4;

    if (t > 0){
        const float4* ws = reinterpret_cast<const float4*>(W_rhh + (size_t)r*H_*H_) + gq*8;
        float4* dw = reinterpret_cast<float4*>(sw);
#pragma unroll
        for (int it=0; it<8; it++){
            int q = tid + it*128;
            int k = q >> 3, c4 = q & 7;
            dw[q] = __ldcg(ws + (size_t)k*32 + c4);
        }
        const float4* msrc = reinterpret_cast<const float4*>(g_msg + (size_t)r*COLS_);
        float4* dm = reinterpret_cast<float4*>(sms);
#pragma unroll
        for (int it=0; it<8; it++) dm[tid + it*128] = __ldcg(msrc + tid + it*128);
        __syncthreads();
    }

    u64 a0,a1,a2,a3;
    {
        ulonglong2 p0 = *reinterpret_cast<const ulonglong2*>(
            g_P + (size_t)r*4096 + (size_t)b0*H_ + g0);
        ulonglong2 p1 = *reinterpret_cast<const ulonglong2*>(
            g_P + (size_t)r*4096 + (size_t)(b0+1)*H_ + g0);
        a0=p0.x; a1=p0.y; a2=p1.x; a3=p1.y;
    }
    if (t > 0){
        const ulonglong2* wu = reinterpret_cast<const ulonglong2*>(sw);
#pragma unroll 4
        for (int k=0;k<H_;k++){
            ulonglong2 w = wu[k*8 + gi];
            float2 mp = sms[k*16 + bp];
            u64 m0 = pk2(mp.x,mp.x), m1 = pk2(mp.y,mp.y);
            a0 = fma2(w.x, m0, a0);  a1 = fma2(w.y, m0, a1);
            a2 = fma2(w.x, m1, a2);  a3 = fma2(w.y, m1, a3);
        }
    }
    float d0,d1,d2,d3, e0,e1,e2,e3;
    up2(a0,d0,d1); up2(a1,d2,d3); up2(a2,e0,e1); up2(a3,e2,e3);
    d0=tanha(d0); d1=tanha(d1); d2=tanha(d2); d3=tanha(d3);
    e0=tanha(e0); e1=tanha(e1); e2=tanha(e2); e3=tanha(e3);

    float* Hbr = g_Hbr + (size_t)t*B_*RH_ + (size_t)r*H_;
    __stcg(reinterpret_cast<float4*>(Hbr + (size_t)b0*RH_ + g0),
           make_float4(d0,d1,d2,d3));
    __stcg(reinterpret_cast<float4*>(Hbr + (size_t)(b0+1)*RH_ + g0),
           make_float4(e0,e1,e2,e3));
    float* Hkb = g_Hkb + ((size_t)t*R_ + r)*COLS_;
    __stcg(reinterpret_cast<float2*>(Hkb + (g0+0)*32 + b0), make_float2(d0,e0));
    __stcg(reinterpret_cast<float2*>(Hkb + (g0+1)*32 + b0), make_float2(d1,e1));
    __stcg(reinterpret_cast<float2*>(Hkb + (g0+2)*32 + b0), make_float2(d2,e2));
    __stcg(reinterpret_cast<float2*>(Hkb + (g0+3)*32 + b0), make_float2(d3,e3));
}

// ============================================================================
// out[t,b,o] = H[t][b][:] @ W_out + b_out   grid (T,2), 128 thr
// ============================================================================
__global__ __launch_bounds__(128) void out_kernel(const float* __restrict__ W_out,
                                                  const float* __restrict__ b_out,
                                                  float* __restrict__ out){
    int t = blockIdx.x, bh = blockIdx.y;
    __shared__ u64 hsh[128][9];
    int tid = threadIdx.x;
    int og = tid & 15, rp = tid >> 4;
    int o0 = og*4;
    u64 acc[4];
    {
        const u64* bo = reinterpret_cast<const u64*>(b_out + o0);
        acc[0]=bo[0]; acc[1]=bo[1]; acc[2]=bo[0]; acc[3]=bo[1];
    }
    const float* Hb = g_Hbr + (size_t)t*B_*RH_ + (size_t)(bh*16)*RH_;
    for (int kt=0; kt<RH_/128; kt++){
        __syncthreads();
        for (int idx = tid; idx < 16*128; idx += 128){
            int b = idx >> 7, kk = idx & 127;
            reinterpret_cast<float*>(&hsh[kk][b>>1])[b&1] = Hb[(size_t)b*RH_ + kt*128 + kk];
        }
        __syncthreads();
#pragma unroll 4
        for (int kk=0; kk<128; kk++){
            int k = kt*128 + kk;
            ulonglong2 w = *reinterpret_cast<const ulonglong2*>(W_out + (size_t)k*O_ + o0);
            u64 hp = hsh[kk][rp];
            float h0, h1; up2(hp, h0, h1);
            u64 h0d = pk2(h0,h0), h1d = pk2(h1,h1);
            acc[0] = fma2(w.x, h0d, acc[0]);  acc[1] = fma2(w.y, h0d, acc[1]);
            acc[2] = fma2(w.x, h1d, acc[2]);  acc[3] = fma2(w.y, h1d, acc[3]);
        }
    }
    u64* op = reinterpret_cast<u64*>(out);
    int row0 = bh*16 + rp*2;
    size_t base0 = ((size_t)(t*B_ + row0  )*O_ + o0) >> 1;
    size_t base1 = ((size_t)(t*B_ + row0+1)*O_ + o0) >> 1;
    op[base0] = acc[0];  op[base0+1] = acc[1];
    op[base1] = acc[2];  op[base1+1] = acc[3];
}

// ============================================================================
// Launch: xprep, 128 x (K1 -> K2) hw-synced graph nodes, out.
// ============================================================================
extern "C" void kernel_launch(void* const* d_in, const int* in_sizes, int n_in,
                              void* d_out, int out_size){
    const float* x     = (const float*)d_in[0];
    const float* C     = (const float*)d_in[1];
    const float* W_ih  = (const float*)d_in[2];
    const float* W_hh  = (const float*)d_in[3];
    const float* W_rhh = (const float*)d_in[4];
    const float* bias  = (const float*)d_in[5];
    const float* W_out = (const float*)d_in[6];
    const float* b_out = (const float*)d_in[7];
    float* out = (float*)d_out;

    cudaFuncSetAttribute(k1_kernel, cudaFuncAttributeMaxDynamicSharedMemorySize,
                         K1_SMEM_FLOATS * (int)sizeof(float));

    xprep_kernel<<<T_, 256>>>(x);

    for (int t = 0; t < T_; t++){
        k1_kernel<<<528, 128, K1_SMEM_FLOATS * sizeof(float)>>>(W_ih, W_hh, C, bias, t);
        k2_kernel<<<400, 128, K2_SMEM_FLOATS * sizeof(float)>>>(W_rhh, t);
    }

    out_kernel<<<dim3(T_, 2), 128>>>(W_out, b_out, out);
}